// round 3
// baseline (speedup 1.0000x reference)
#include <cuda_runtime.h>
#include <cuda_bf16.h>

#define BDIM   8
#define SDIM   4096
#define HDIM   16
#define PDIM   64
#define NDIM   64
#define LCHUNK 64
#define NCHUNK 64
#define NBH    (BDIM * HDIM)   // 128
#define SPLIT  8               // chunk-parallel blocks per (b,h)
#define THRESH 40.0f

// Scratch (allocation-free rule: __device__ globals)
__device__ float g_w[NBH * SDIM];                      // per-t decay weights
__device__ int   g_start[NBH];                         // first active chunk
__device__ float g_part[SPLIT * NBH * PDIM * NDIM];    // partial sums (16MB)

// Packed-f32 FMA helpers (sm_100+: fma.rn.f32x2)
__device__ __forceinline__ void ffma2(unsigned long long& d,
                                      unsigned long long a,
                                      unsigned long long b) {
    asm("fma.rn.f32x2 %0, %1, %2, %0;" : "+l"(d) : "l"(a), "l"(b));
}
__device__ __forceinline__ unsigned long long pack2(float lo, float hi) {
    unsigned long long r;
    asm("mov.b64 %0, {%1, %2};" : "=l"(r) : "f"(lo), "f"(hi));
    return r;
}
__device__ __forceinline__ void unpack2(unsigned long long v, float& lo, float& hi) {
    asm("mov.b64 {%0, %1}, %2;" : "=f"(lo), "=f"(hi) : "l"(v));
}

union F4U2 { float4 f4; unsigned long long u2[2]; };

// ---------------------------------------------------------------------------
// Prep (parallel): chunk totals (4 thr/chunk), suffix scan (warp 0),
// weights via per-warp pair-scan, coalesced float2 stores.
// Grid: NBH blocks x 256 threads.
// ---------------------------------------------------------------------------
__global__ void __launch_bounds__(256) prep_kernel(const float* __restrict__ A) {
    const int bh   = blockIdx.x;
    const int b    = bh >> 4;
    const int h    = bh & 15;
    const int tid  = threadIdx.x;
    const int lane = tid & 31;
    const int warp = tid >> 5;

    __shared__ float Tj[NCHUNK];
    __shared__ float Uj[NCHUNK];
    __shared__ int   s_start;

    const float* Ab = A + (long)b * SDIM * HDIM + h;

    // Phase 1: chunk totals, 4 threads per chunk (16 strided loads each)
    {
        const int j = tid >> 2, q = tid & 3;
        const int t0 = j * LCHUNK + q * 16;
        float s = 0.0f;
        #pragma unroll
        for (int i = 0; i < 16; i++) s += Ab[(t0 + i) * HDIM];
        s += __shfl_down_sync(0xffffffffu, s, 2);
        s += __shfl_down_sync(0xffffffffu, s, 1);
        if (q == 0) Tj[j] = s;
    }
    if (tid == 0) s_start = NCHUNK - 1;
    __syncthreads();

    // Phase 2: suffix sums via reversed inclusive warp scan (warp 0, 2 chunks/lane)
    if (warp == 0) {
        const int r0 = 2 * lane, r1 = 2 * lane + 1;    // reversed indices
        const float a0 = Tj[63 - r0];
        const float a1 = Tj[63 - r1];
        const float ps = a0 + a1;
        float sc = ps;
        #pragma unroll
        for (int d = 1; d < 32; d <<= 1) {
            float o = __shfl_up_sync(0xffffffffu, sc, d);
            if (lane >= d) sc += o;
        }
        const float P1 = sc;        // inclusive through r1
        const float P0 = sc - a1;   // inclusive through r0
        Uj[63 - r0] = P0 - a0;      // sum of totals of chunks > (63-r0)
        Uj[63 - r1] = P1 - a1;
    }
    __syncthreads();

    // Start detection: smallest k with Uj[k] > -THRESH
    if (tid < NCHUNK && Uj[tid] > -THRESH) atomicMin(&s_start, tid);
    __syncthreads();
    const int start = s_start;
    if (tid == 0) g_start[bh] = start;

    // Phase 3: weights for active chunks. Warp w handles chunk start+w (+8,...)
    for (int j = start + warp; j < NCHUNK; j += 8) {
        const int t0 = j * LCHUNK;
        const float a0 = Ab[(t0 + 2 * lane)     * HDIM];
        const float a1 = Ab[(t0 + 2 * lane + 1) * HDIM];
        const float ps = a0 + a1;
        float sc = ps;
        #pragma unroll
        for (int d = 1; d < 32; d <<= 1) {
            float o = __shfl_up_sync(0xffffffffu, sc, d);
            if (lane >= d) sc += o;
        }
        const float cs1 = sc;        // inclusive cumsum through t0+2*lane+1
        const float cs0 = sc - a1;   // inclusive cumsum through t0+2*lane
        const float base = Uj[j] + Tj[j];
        float2 wv;
        wv.x = expf(base - cs0);
        wv.y = expf(base - cs1);
        ((float2*)(g_w + bh * SDIM + t0))[lane] = wv;
    }
}

// ---------------------------------------------------------------------------
// Main: grid (NBH, SPLIT), 64 threads, 8x8 register tile per thread.
// acc packed over p-pairs (natural float4 halves), b duplicated via MOV.
// ---------------------------------------------------------------------------
__global__ void __launch_bounds__(64)
mamba_state_kernel(const float* __restrict__ X,
                   const float* __restrict__ B,
                   float* __restrict__ part) {
    __shared__ float xs[LCHUNK][PDIM];   // w-scaled X tile [l][p]
    __shared__ float bs[LCHUNK][NDIM];   // B tile [l][n]

    const int bh  = blockIdx.x;
    const int k0  = blockIdx.y;
    const int b   = bh >> 4;
    const int h   = bh & 15;
    const int tid = threadIdx.x;
    const int tp  = tid >> 3;            // 0..7: p-group (8 rows)
    const int tn  = tid & 7;             // 0..7: n-group (8 cols)

    const int j0 = g_start[bh];

    const float4* X4 = (const float4*)X;
    const float4* B4 = (const float4*)B;
    const float*  wrow = g_w + bh * SDIM;

    // acc2[pi][n]: 64-bit = (out[tp*8+2pi, tn*8+n], out[tp*8+2pi+1, tn*8+n])
    unsigned long long acc2[4][8];
    #pragma unroll
    for (int i = 0; i < 4; i++)
        #pragma unroll
        for (int n = 0; n < 8; n++) acc2[i][n] = 0ull;

    for (int j = j0 + k0; j < NCHUNK; j += SPLIT) {
        const int t0 = j * LCHUNK;
        // Load tile: 1024 float4s (x and b), 16 per thread, coalesced
        #pragma unroll
        for (int k = 0; k < 16; k++) {
            const int idx = k * 64 + tid;
            const int row = idx >> 4;
            const int col = idx & 15;
            const int t   = t0 + row;
            const int base = ((b * SDIM + t) * HDIM + h) * 16 + col;
            float4 xv = X4[base];
            const float4 bv = B4[base];
            const float w = wrow[t];
            xv.x *= w; xv.y *= w; xv.z *= w; xv.w *= w;
            *(float4*)&xs[row][col * 4] = xv;
            *(float4*)&bs[row][col * 4] = bv;
        }
        __syncthreads();

        #pragma unroll 2
        for (int l = 0; l < LCHUNK; l++) {
            F4U2 xa, xb, ba, bb;
            xa.f4 = *(const float4*)&xs[l][tp * 8];
            xb.f4 = *(const float4*)&xs[l][tp * 8 + 4];
            ba.f4 = *(const float4*)&bs[l][tn * 8];
            bb.f4 = *(const float4*)&bs[l][tn * 8 + 4];
            // duplicate b scalars into packed pairs (ALU pipe)
            unsigned long long bd[8];
            bd[0] = pack2(ba.f4.x, ba.f4.x);
            bd[1] = pack2(ba.f4.y, ba.f4.y);
            bd[2] = pack2(ba.f4.z, ba.f4.z);
            bd[3] = pack2(ba.f4.w, ba.f4.w);
            bd[4] = pack2(bb.f4.x, bb.f4.x);
            bd[5] = pack2(bb.f4.y, bb.f4.y);
            bd[6] = pack2(bb.f4.z, bb.f4.z);
            bd[7] = pack2(bb.f4.w, bb.f4.w);
            // a-operands: natural 64-bit halves of the float4 loads
            #pragma unroll
            for (int n = 0; n < 8; n++) {
                ffma2(acc2[0][n], xa.u2[0], bd[n]);
                ffma2(acc2[1][n], xa.u2[1], bd[n]);
                ffma2(acc2[2][n], xb.u2[0], bd[n]);
                ffma2(acc2[3][n], xb.u2[1], bd[n]);
            }
        }
        __syncthreads();
    }

    // Write partials: part[k0][bh][p][n]  (always write — zeros if no chunks)
    float4* out4 = (float4*)g_part + ((long)k0 * NBH + bh) * PDIM * 16;
    (void)part;
    #pragma unroll
    for (int pi = 0; pi < 4; pi++) {
        const int p0 = tp * 8 + 2 * pi;
        float4 v0a, v0b, v1a, v1b;
        unpack2(acc2[pi][0], v0a.x, v1a.x);
        unpack2(acc2[pi][1], v0a.y, v1a.y);
        unpack2(acc2[pi][2], v0a.z, v1a.z);
        unpack2(acc2[pi][3], v0a.w, v1a.w);
        unpack2(acc2[pi][4], v0b.x, v1b.x);
        unpack2(acc2[pi][5], v0b.y, v1b.y);
        unpack2(acc2[pi][6], v0b.z, v1b.z);
        unpack2(acc2[pi][7], v0b.w, v1b.w);
        out4[p0 * 16 + tn * 2]           = v0a;
        out4[p0 * 16 + tn * 2 + 1]       = v0b;
        out4[(p0 + 1) * 16 + tn * 2]     = v1a;
        out4[(p0 + 1) * 16 + tn * 2 + 1] = v1b;
    }
}

// ---------------------------------------------------------------------------
// Reduce: out = sum over SPLIT partials. Deterministic.
// ---------------------------------------------------------------------------
__global__ void reduce_kernel(const float* __restrict__ part,
                              float* __restrict__ out) {
    const int i = blockIdx.x * 256 + threadIdx.x;     // float4 index
    const int STRIDE = NBH * PDIM * NDIM / 4;         // 131072
    const float4* p4 = (const float4*)part;
    float4 s = p4[i];
    #pragma unroll
    for (int k = 1; k < SPLIT; k++) {
        float4 v = p4[i + k * STRIDE];
        s.x += v.x; s.y += v.y; s.z += v.z; s.w += v.w;
    }
    ((float4*)out)[i] = s;
}

// ---------------------------------------------------------------------------
extern "C" void kernel_launch(void* const* d_in, const int* in_sizes, int n_in,
                              void* d_out, int out_size) {
    const float* X = (const float*)d_in[0];
    const float* A = (const float*)d_in[1];
    const float* B = (const float*)d_in[2];
    float* out = (float*)d_out;

    float* part;
    cudaGetSymbolAddress((void**)&part, g_part);

    prep_kernel<<<NBH, 256>>>(A);
    dim3 grid(NBH, SPLIT);
    mamba_state_kernel<<<grid, 64>>>(X, B, part);
    reduce_kernel<<<NBH * PDIM * NDIM / 4 / 256, 256>>>(part, out);
}